// round 1
// baseline (speedup 1.0000x reference)
#include <cuda_runtime.h>
#include <cuda_bf16.h>
#include <cstdint>

// Problem constants
#define Bsz 16
#define Sq 2048
#define Hd 1024
#define NSP 64
#define NROWS (Bsz * NSP)      // 1024
#define NC 4096
#define ARC_SCALE 30.0f
#define COS_M 0.8775825618903728f
#define SIN_M 0.479425538604203f
#define TH_C (-0.8775825618903728f)
#define MM_C 0.2397127693021015f
#define LN_EPS 1e-7f

// ---------------- scratch (no allocations allowed) ----------------
__device__ __nv_bfloat16 g_emb[NROWS * Hd];        // 2 MB  normalized span embeddings
__device__ __nv_bfloat16 g_w[NC * Hd];             // 8 MB  normalized arc weights
__device__ float g_cos[(size_t)NROWS * NC];        // 16 MB cosine matrix
__device__ float g_nll[NROWS];

// ---------------- reductions ----------------
__device__ __forceinline__ float blockReduceSum(float v, float* sbuf) {
    int lane = threadIdx.x & 31, wid = threadIdx.x >> 5;
#pragma unroll
    for (int o = 16; o; o >>= 1) v += __shfl_down_sync(0xffffffffu, v, o);
    if (lane == 0) sbuf[wid] = v;
    __syncthreads();
    if (wid == 0) {
        v = (lane < 8) ? sbuf[lane] : 0.f;
#pragma unroll
        for (int o = 4; o; o >>= 1) v += __shfl_down_sync(0xffffffffu, v, o);
        if (lane == 0) sbuf[0] = v;
    }
    __syncthreads();
    float r = sbuf[0];
    __syncthreads();
    return r;
}

__device__ __forceinline__ float blockReduceMax(float v, float* sbuf) {
    int lane = threadIdx.x & 31, wid = threadIdx.x >> 5;
#pragma unroll
    for (int o = 16; o; o >>= 1) v = fmaxf(v, __shfl_down_sync(0xffffffffu, v, o));
    if (lane == 0) sbuf[wid] = v;
    __syncthreads();
    if (wid == 0) {
        v = (lane < 8) ? sbuf[lane] : -3.4e38f;
#pragma unroll
        for (int o = 4; o; o >>= 1) v = fmaxf(v, __shfl_down_sync(0xffffffffu, v, o));
        if (lane == 0) sbuf[0] = v;
    }
    __syncthreads();
    float r = sbuf[0];
    __syncthreads();
    return r;
}

// ---------------- K1: span mean + layernorm + l2norm -> bf16 ----------------
__global__ __launch_bounds__(256) void span_kernel(
    const float* __restrict__ enc, const float* __restrict__ gamma,
    const float* __restrict__ beta, const int* __restrict__ heads,
    const int* __restrict__ tails) {
    __shared__ float sbuf[8];
    int row = blockIdx.x;           // b*64 + span
    int b = row >> 6;
    int tid = threadIdx.x;          // 256 threads, each owns 4 consecutive H dims
    int head = heads[row], tail = tails[row];
    float inv_len = 1.f / (float)(tail - head);

    const float4* base = (const float4*)enc + (size_t)b * Sq * (Hd / 4) + tid;
    float4 acc = make_float4(0.f, 0.f, 0.f, 0.f);
    for (int t = head; t < tail; ++t) {
        float4 v = base[(size_t)t * (Hd / 4)];
        acc.x += v.x; acc.y += v.y; acc.z += v.z; acc.w += v.w;
    }
    float x0 = acc.x * inv_len, x1 = acc.y * inv_len, x2 = acc.z * inv_len, x3 = acc.w * inv_len;

    float s1 = blockReduceSum(x0 + x1 + x2 + x3, sbuf);
    float s2 = blockReduceSum(x0 * x0 + x1 * x1 + x2 * x2 + x3 * x3, sbuf);
    float mu = s1 * (1.f / Hd);
    float var = s2 * (1.f / Hd) - mu * mu;
    float rs = rsqrtf(var + LN_EPS);

    float4 gm = ((const float4*)gamma)[tid];
    float4 bt = ((const float4*)beta)[tid];
    float y0 = (x0 - mu) * rs * gm.x + bt.x;
    float y1 = (x1 - mu) * rs * gm.y + bt.y;
    float y2 = (x2 - mu) * rs * gm.z + bt.z;
    float y3 = (x3 - mu) * rs * gm.w + bt.w;

    float s3 = blockReduceSum(y0 * y0 + y1 * y1 + y2 * y2 + y3 * y3, sbuf);
    float inv_nrm = 1.f / fmaxf(sqrtf(s3), 1e-12f);

    __nv_bfloat16* dst = g_emb + (size_t)row * Hd + tid * 4;
    dst[0] = __float2bfloat16_rn(y0 * inv_nrm);
    dst[1] = __float2bfloat16_rn(y1 * inv_nrm);
    dst[2] = __float2bfloat16_rn(y2 * inv_nrm);
    dst[3] = __float2bfloat16_rn(y3 * inv_nrm);
}

// ---------------- K2: arc weight row l2-norm -> bf16 ----------------
__global__ __launch_bounds__(256) void wnorm_kernel(const float* __restrict__ w) {
    __shared__ float sbuf[8];
    int row = blockIdx.x;
    int tid = threadIdx.x;
    float4 v = ((const float4*)w)[(size_t)row * (Hd / 4) + tid];
    float s = blockReduceSum(v.x * v.x + v.y * v.y + v.z * v.z + v.w * v.w, sbuf);
    float inv_nrm = 1.f / fmaxf(sqrtf(s), 1e-12f);
    __nv_bfloat16* dst = g_w + (size_t)row * Hd + tid * 4;
    dst[0] = __float2bfloat16_rn(v.x * inv_nrm);
    dst[1] = __float2bfloat16_rn(v.y * inv_nrm);
    dst[2] = __float2bfloat16_rn(v.z * inv_nrm);
    dst[3] = __float2bfloat16_rn(v.w * inv_nrm);
}

// ---------------- K3: cosine = emb_n @ w_n^T  (bf16 mma.sync, fp32 acc) -----
#define BM 128
#define BN 128
#define BK 32
#define LDT 40   // BK + 8 pad (20 banks stride -> conflict-free fragment reads)

__device__ __forceinline__ void cp16(void* smem_dst, const void* gsrc) {
    uint32_t d = (uint32_t)__cvta_generic_to_shared(smem_dst);
    asm volatile("cp.async.cg.shared.global [%0], [%1], 16;\n" ::"r"(d), "l"(gsrc));
}

__device__ __forceinline__ void issue_tile(
    __nv_bfloat16* As, __nv_bfloat16* Bs, int bm0, int bn0, int k0, int tid) {
#pragma unroll
    for (int c = 0; c < 2; c++) {
        int ca = tid + c * 256;          // 0..511
        int r = ca >> 2, kc = ca & 3;    // row 0..127, 8-elem chunk 0..3
        cp16(&As[r * LDT + kc * 8], g_emb + (size_t)(bm0 + r) * Hd + k0 + kc * 8);
        cp16(&Bs[r * LDT + kc * 8], g_w + (size_t)(bn0 + r) * Hd + k0 + kc * 8);
    }
    asm volatile("cp.async.commit_group;\n");
}

__global__ __launch_bounds__(256) void gemm_kernel() {
    __shared__ __nv_bfloat16 As[2][BM * LDT];
    __shared__ __nv_bfloat16 Bs[2][BN * LDT];

    int tid = threadIdx.x;
    int bm0 = blockIdx.y * BM, bn0 = blockIdx.x * BN;
    int wid = tid >> 5, lane = tid & 31;
    int wm = (wid >> 2) * 64;   // warp row offset (2 warps in M)
    int wn = (wid & 3) * 32;    // warp col offset (4 warps in N)
    int fr = lane >> 2, fc = (lane & 3) * 2;   // fragment row / col-pair

    float acc[4][4][4];
#pragma unroll
    for (int i = 0; i < 4; i++)
#pragma unroll
        for (int j = 0; j < 4; j++)
#pragma unroll
            for (int e = 0; e < 4; e++) acc[i][j][e] = 0.f;

    const int NK = Hd / BK;  // 32
    issue_tile(As[0], Bs[0], bm0, bn0, 0, tid);

    for (int kt = 0; kt < NK; kt++) {
        int st = kt & 1;
        if (kt + 1 < NK) {
            issue_tile(As[st ^ 1], Bs[st ^ 1], bm0, bn0, (kt + 1) * BK, tid);
            asm volatile("cp.async.wait_group 1;\n");
        } else {
            asm volatile("cp.async.wait_group 0;\n");
        }
        __syncthreads();

#pragma unroll
        for (int ks = 0; ks < 2; ks++) {
            int k0 = ks * 16;
            uint32_t a[4][4], bfr[4][2];
#pragma unroll
            for (int mi = 0; mi < 4; mi++) {
                const __nv_bfloat16* p = &As[st][(wm + mi * 16 + fr) * LDT + k0 + fc];
                a[mi][0] = *(const uint32_t*)p;
                a[mi][1] = *(const uint32_t*)(p + 8 * LDT);
                a[mi][2] = *(const uint32_t*)(p + 8);
                a[mi][3] = *(const uint32_t*)(p + 8 * LDT + 8);
            }
#pragma unroll
            for (int ni = 0; ni < 4; ni++) {
                const __nv_bfloat16* p = &Bs[st][(wn + ni * 8 + fr) * LDT + k0 + fc];
                bfr[ni][0] = *(const uint32_t*)p;
                bfr[ni][1] = *(const uint32_t*)(p + 8);
            }
#pragma unroll
            for (int mi = 0; mi < 4; mi++)
#pragma unroll
                for (int ni = 0; ni < 4; ni++) {
                    float* c = acc[mi][ni];
                    asm volatile(
                        "mma.sync.aligned.m16n8k16.row.col.f32.bf16.bf16.f32 "
                        "{%0,%1,%2,%3}, {%4,%5,%6,%7}, {%8,%9}, {%0,%1,%2,%3};"
                        : "+f"(c[0]), "+f"(c[1]), "+f"(c[2]), "+f"(c[3])
                        : "r"(a[mi][0]), "r"(a[mi][1]), "r"(a[mi][2]), "r"(a[mi][3]),
                          "r"(bfr[ni][0]), "r"(bfr[ni][1]));
                }
        }
        __syncthreads();
    }

    // epilogue: fp32 cosine, row-major [NROWS, NC]
#pragma unroll
    for (int mi = 0; mi < 4; mi++)
#pragma unroll
        for (int ni = 0; ni < 4; ni++) {
            int gr = bm0 + wm + mi * 16 + fr;
            int gc = bn0 + wn + ni * 8 + fc;
            float* o0 = g_cos + (size_t)gr * NC + gc;
            float* o1 = g_cos + (size_t)(gr + 8) * NC + gc;
            *(float2*)o0 = make_float2(acc[mi][ni][0], acc[mi][ni][1]);
            *(float2*)o1 = make_float2(acc[mi][ni][2], acc[mi][ni][3]);
        }
}

// ---------------- K4: arcface margin + row logsumexp -> nll ----------------
__global__ __launch_bounds__(256) void nll_kernel(const int* __restrict__ labels) {
    __shared__ float sbuf[8];
    __shared__ float sLab;
    int row = blockIdx.x;
    int tid = threadIdx.x;
    int lab = labels[row];

    const float4* crow = (const float4*)(g_cos + (size_t)row * NC);
    float v[16];
    float mx = -3.4e38f;
#pragma unroll
    for (int i = 0; i < 4; i++) {
        int idx = i * 256 + tid;
        float4 c4 = crow[idx];
        float cs[4] = {c4.x, c4.y, c4.z, c4.w};
#pragma unroll
        for (int e = 0; e < 4; e++) {
            int j = idx * 4 + e;
            float c = cs[e];
            float logit;
            if (j == lab) {
                float sn = sqrtf(fmaxf(0.f, 1.f - c * c));
                float phi = c * COS_M - sn * SIN_M;
                if (!(c > TH_C)) phi = c - MM_C;
                logit = phi * ARC_SCALE;
                sLab = logit;
            } else {
                logit = c * ARC_SCALE;
            }
            v[i * 4 + e] = logit;
            mx = fmaxf(mx, logit);
        }
    }
    float m = blockReduceMax(mx, sbuf);
    float se = 0.f;
#pragma unroll
    for (int i = 0; i < 16; i++) se += __expf(v[i] - m);
    float tot = blockReduceSum(se, sbuf);
    if (tid == 0) g_nll[row] = m + logf(tot) - sLab;
}

// ---------------- K5: mean over rows ----------------
__global__ __launch_bounds__(256) void mean_kernel(float* __restrict__ out) {
    __shared__ float sbuf[8];
    float s = 0.f;
    for (int i = threadIdx.x; i < NROWS; i += 256) s += g_nll[i];
    float tot = blockReduceSum(s, sbuf);
    if (threadIdx.x == 0) out[0] = tot * (1.f / NROWS);
}

// ---------------- launch ----------------
extern "C" void kernel_launch(void* const* d_in, const int* in_sizes, int n_in,
                              void* d_out, int out_size) {
    const float* enc = (const float*)d_in[0];
    const float* gamma = (const float*)d_in[1];
    const float* beta = (const float*)d_in[2];
    const float* arc_w = (const float*)d_in[3];
    const int* heads = (const int*)d_in[4];
    const int* tails = (const int*)d_in[5];
    const int* labels = (const int*)d_in[6];
    float* out = (float*)d_out;

    span_kernel<<<NROWS, 256>>>(enc, gamma, beta, heads, tails);
    wnorm_kernel<<<NC, 256>>>(arc_w);
    gemm_kernel<<<dim3(NC / BN, NROWS / BM), 256>>>();
    nll_kernel<<<NROWS, 256>>>(labels);
    mean_kernel<<<1, 256>>>(out);
}

// round 3
// speedup vs baseline: 1.1635x; 1.1635x over previous
#include <cuda_runtime.h>
#include <cuda_bf16.h>
#include <cstdint>

// Problem constants
#define Bsz 16
#define Sq 2048
#define Hd 1024
#define NSP 64
#define NROWS (Bsz * NSP)      // 1024
#define NC 4096
#define ARC_SCALE 30.0f
#define COS_M 0.8775825618903728f
#define SIN_M 0.479425538604203f
#define TH_C (-0.8775825618903728f)
#define MM_C 0.2397127693021015f
#define LN_EPS 1e-7f

// ---------------- scratch (no allocations allowed) ----------------
__device__ __nv_bfloat16 g_emb[NROWS * Hd];   // normalized span embeddings (bf16)
__device__ __nv_bfloat16 g_w[NC * Hd];        // normalized arc weights (bf16)
__device__ float g_rowsum[NROWS];             // per-row sum exp(logit - 30)
__device__ float g_lablogit[NROWS];           // per-row label logit (30*phi)

// ---------------- reductions ----------------
__device__ __forceinline__ float blockReduceSum(float v, float* sbuf) {
    int lane = threadIdx.x & 31, wid = threadIdx.x >> 5;
#pragma unroll
    for (int o = 16; o; o >>= 1) v += __shfl_down_sync(0xffffffffu, v, o);
    if (lane == 0) sbuf[wid] = v;
    __syncthreads();
    if (wid == 0) {
        v = (lane < 8) ? sbuf[lane] : 0.f;
#pragma unroll
        for (int o = 4; o; o >>= 1) v += __shfl_down_sync(0xffffffffu, v, o);
        if (lane == 0) sbuf[0] = v;
    }
    __syncthreads();
    float r = sbuf[0];
    __syncthreads();
    return r;
}

// ---------------- K1: fused prep (span mean+LN+L2  |  weight L2) -----------
__global__ __launch_bounds__(256) void prep_kernel(
    const float* __restrict__ enc, const float* __restrict__ gamma,
    const float* __restrict__ beta, const int* __restrict__ heads,
    const int* __restrict__ tails, const float* __restrict__ w) {
    __shared__ float sbuf[8];
    int tid = threadIdx.x;

    if (blockIdx.x < NROWS) {
        // ---- span path ----
        int row = blockIdx.x;
        int b = row >> 6;
        int head = heads[row], tail = tails[row];
        float inv_len = 1.f / (float)(tail - head);

        const float4* base = (const float4*)enc + (size_t)b * Sq * (Hd / 4) + tid;
        float4 acc = make_float4(0.f, 0.f, 0.f, 0.f);
        for (int t = head; t < tail; ++t) {
            float4 v = base[(size_t)t * (Hd / 4)];
            acc.x += v.x; acc.y += v.y; acc.z += v.z; acc.w += v.w;
        }
        float x0 = acc.x * inv_len, x1 = acc.y * inv_len;
        float x2 = acc.z * inv_len, x3 = acc.w * inv_len;

        float s1 = blockReduceSum(x0 + x1 + x2 + x3, sbuf);
        float s2 = blockReduceSum(x0 * x0 + x1 * x1 + x2 * x2 + x3 * x3, sbuf);
        float mu = s1 * (1.f / Hd);
        float var = s2 * (1.f / Hd) - mu * mu;
        float rs = rsqrtf(var + LN_EPS);

        float4 gm = ((const float4*)gamma)[tid];
        float4 bt = ((const float4*)beta)[tid];
        float y0 = (x0 - mu) * rs * gm.x + bt.x;
        float y1 = (x1 - mu) * rs * gm.y + bt.y;
        float y2 = (x2 - mu) * rs * gm.z + bt.z;
        float y3 = (x3 - mu) * rs * gm.w + bt.w;

        float s3 = blockReduceSum(y0 * y0 + y1 * y1 + y2 * y2 + y3 * y3, sbuf);
        float inv_nrm = 1.f / fmaxf(sqrtf(s3), 1e-12f);

        __nv_bfloat16* dst = g_emb + (size_t)row * Hd + tid * 4;
        dst[0] = __float2bfloat16_rn(y0 * inv_nrm);
        dst[1] = __float2bfloat16_rn(y1 * inv_nrm);
        dst[2] = __float2bfloat16_rn(y2 * inv_nrm);
        dst[3] = __float2bfloat16_rn(y3 * inv_nrm);
        if (tid == 0) g_rowsum[row] = 0.f;
    } else {
        // ---- weight-norm path ----
        int row = blockIdx.x - NROWS;
        float4 v = ((const float4*)w)[(size_t)row * (Hd / 4) + tid];
        float s = blockReduceSum(v.x * v.x + v.y * v.y + v.z * v.z + v.w * v.w, sbuf);
        float inv_nrm = 1.f / fmaxf(sqrtf(s), 1e-12f);
        __nv_bfloat16* dst = g_w + (size_t)row * Hd + tid * 4;
        dst[0] = __float2bfloat16_rn(v.x * inv_nrm);
        dst[1] = __float2bfloat16_rn(v.y * inv_nrm);
        dst[2] = __float2bfloat16_rn(v.z * inv_nrm);
        dst[3] = __float2bfloat16_rn(v.w * inv_nrm);
    }
}

// ---------------- K2: HMMA GEMM + fused arcface/sumexp epilogue ------------
#define BM 128
#define BN 256
#define BK 32
#define LDT 40                 // padded smem row stride (elements)
#define NSTG 3
#define NKT (Hd / BK)          // 32
#define STG_ELEMS ((BM + BN) * LDT)
#define DSMEM_BYTES (NSTG * STG_ELEMS * 2)

__device__ __forceinline__ void cp16(uint32_t smem_dst, const void* gsrc) {
    asm volatile("cp.async.cg.shared.global [%0], [%1], 16;\n" ::"r"(smem_dst), "l"(gsrc));
}

__device__ __forceinline__ void cp_stage(uint32_t a_base, uint32_t b_base,
                                         int bm0, int bn0, int kt, int tid) {
    int k0 = kt * BK;
#pragma unroll
    for (int i = 0; i < 2; i++) {            // A: 128 rows x 4 16B chunks
        int idx = tid + i * 256;
        int r = idx >> 2, c = idx & 3;
        cp16(a_base + r * (LDT * 2) + c * 16,
             g_emb + (size_t)(bm0 + r) * Hd + k0 + c * 8);
    }
#pragma unroll
    for (int i = 0; i < 4; i++) {            // B: 256 rows x 4 chunks
        int idx = tid + i * 256;
        int r = idx >> 2, c = idx & 3;
        cp16(b_base + r * (LDT * 2) + c * 16,
             g_w + (size_t)(bn0 + r) * Hd + k0 + c * 8);
    }
    asm volatile("cp.async.commit_group;\n" ::: "memory");
}

__global__ __launch_bounds__(256, 1) void gemm_fused(const int* __restrict__ labels) {
    extern __shared__ __align__(16) __nv_bfloat16 smem[];
    __shared__ float rowacc[BM];
    __shared__ int slab[BM];

    int tid = threadIdx.x, wid = tid >> 5, lane = tid & 31;
    int bn0 = blockIdx.x * BN, bm0 = blockIdx.y * BM;
    int wm = (wid >> 2) * 64;       // 2 warps in M
    int wn = (wid & 3) * 64;        // 4 warps in N
    int fr = lane >> 2, fc = (lane & 3) * 2;

    if (tid < BM) {
        rowacc[tid] = 0.f;
        slab[tid] = labels[bm0 + tid];
    }

    uint32_t smem_base = (uint32_t)__cvta_generic_to_shared(smem);

    float acc[4][8][4];
#pragma unroll
    for (int i = 0; i < 4; i++)
#pragma unroll
        for (int j = 0; j < 8; j++)
#pragma unroll
            for (int e = 0; e < 4; e++) acc[i][j][e] = 0.f;

    // prologue: fill 3 stages
#pragma unroll
    for (int s = 0; s < NSTG; s++) {
        uint32_t ab = smem_base + s * (STG_ELEMS * 2);
        cp_stage(ab, ab + BM * LDT * 2, bm0, bn0, s, tid);
    }

    for (int kt = 0; kt < NKT; kt++) {
        asm volatile("cp.async.wait_group %0;\n" ::"n"(NSTG - 1) : "memory");
        __syncthreads();

        const __nv_bfloat16* As = smem + (kt % NSTG) * STG_ELEMS;
        const __nv_bfloat16* Bs = As + BM * LDT;

#pragma unroll
        for (int ks = 0; ks < 2; ks++) {
            int k0 = ks * 16;
            uint32_t a[4][4], b[8][2];
#pragma unroll
            for (int mi = 0; mi < 4; mi++) {
                const __nv_bfloat16* p = &As[(wm + mi * 16 + fr) * LDT + k0 + fc];
                a[mi][0] = *(const uint32_t*)p;
                a[mi][1] = *(const uint32_t*)(p + 8 * LDT);
                a[mi][2] = *(const uint32_t*)(p + 8);
                a[mi][3] = *(const uint32_t*)(p + 8 * LDT + 8);
            }
#pragma unroll
            for (int ni = 0; ni < 8; ni++) {
                const __nv_bfloat16* p = &Bs[(wn + ni * 8 + fr) * LDT + k0 + fc];
                b[ni][0] = *(const uint32_t*)p;
                b[ni][1] = *(const uint32_t*)(p + 8);
            }
#pragma unroll
            for (int mi = 0; mi < 4; mi++)
#pragma unroll
                for (int ni = 0; ni < 8; ni++) {
                    float* c = acc[mi][ni];
                    asm volatile(
                        "mma.sync.aligned.m16n8k16.row.col.f32.bf16.bf16.f32 "
                        "{%0,%1,%2,%3}, {%4,%5,%6,%7}, {%8,%9}, {%0,%1,%2,%3};"
                        : "+f"(c[0]), "+f"(c[1]), "+f"(c[2]), "+f"(c[3])
                        : "r"(a[mi][0]), "r"(a[mi][1]), "r"(a[mi][2]), "r"(a[mi][3]),
                          "r"(b[ni][0]), "r"(b[ni][1]));
                }
        }
        __syncthreads();
        if (kt + NSTG < NKT) {
            uint32_t ab = smem_base + ((kt + NSTG) % NSTG) * (STG_ELEMS * 2);
            cp_stage(ab, ab + BM * LDT * 2, bm0, bn0, kt + NSTG, tid);
        }
    }

    // ---- fused epilogue: arcface margin + shifted sum-exp ----
#pragma unroll
    for (int mi = 0; mi < 4; mi++) {
        int lr0 = wm + mi * 16 + fr;       // local rows
        int lr1 = lr0 + 8;
        int lab0 = slab[lr0], lab1 = slab[lr1];
        float s0 = 0.f, s1 = 0.f;
#pragma unroll
        for (int ni = 0; ni < 8; ni++) {
            int gc = bn0 + wn + ni * 8 + fc;
            float* c = acc[mi][ni];
#pragma unroll
            for (int e = 0; e < 2; e++) {
                int col = gc + e;
                // row lr0
                {
                    float cv = c[e];
                    float lg = ARC_SCALE * cv - ARC_SCALE;
                    if (col == lab0) {
                        float sn = sqrtf(fmaxf(0.f, 1.f - cv * cv));
                        float phi = cv * COS_M - sn * SIN_M;
                        if (!(cv > TH_C)) phi = cv - MM_C;
                        lg = ARC_SCALE * phi - ARC_SCALE;
                        g_lablogit[bm0 + lr0] = ARC_SCALE * phi;
                    }
                    s0 += __expf(lg);
                }
                // row lr1
                {
                    float cv = c[2 + e];
                    float lg = ARC_SCALE * cv - ARC_SCALE;
                    if (col == lab1) {
                        float sn = sqrtf(fmaxf(0.f, 1.f - cv * cv));
                        float phi = cv * COS_M - sn * SIN_M;
                        if (!(cv > TH_C)) phi = cv - MM_C;
                        lg = ARC_SCALE * phi - ARC_SCALE;
                        g_lablogit[bm0 + lr1] = ARC_SCALE * phi;
                    }
                    s1 += __expf(lg);
                }
            }
        }
        // quad reduce (lanes sharing fr)
        s0 += __shfl_down_sync(0xffffffffu, s0, 1);
        s0 += __shfl_down_sync(0xffffffffu, s0, 2);
        s1 += __shfl_down_sync(0xffffffffu, s1, 1);
        s1 += __shfl_down_sync(0xffffffffu, s1, 2);
        if ((lane & 3) == 0) {
            atomicAdd(&rowacc[lr0], s0);
            atomicAdd(&rowacc[lr1], s1);
        }
    }
    __syncthreads();
    if (tid < BM) atomicAdd(&g_rowsum[bm0 + tid], rowacc[tid]);
}

// ---------------- K3: final mean over rows ----------------
__global__ __launch_bounds__(256) void finish_kernel(float* __restrict__ out) {
    __shared__ float sbuf[8];
    float s = 0.f;
    for (int i = threadIdx.x; i < NROWS; i += 256)
        s += ARC_SCALE + logf(g_rowsum[i]) - g_lablogit[i];
    float tot = blockReduceSum(s, sbuf);
    if (threadIdx.x == 0) out[0] = tot * (1.f / NROWS);
}

// ---------------- launch ----------------
extern "C" void kernel_launch(void* const* d_in, const int* in_sizes, int n_in,
                              void* d_out, int out_size) {
    const float* enc = (const float*)d_in[0];
    const float* gamma = (const float*)d_in[1];
    const float* beta = (const float*)d_in[2];
    const float* arc_w = (const float*)d_in[3];
    const int* heads = (const int*)d_in[4];
    const int* tails = (const int*)d_in[5];
    const int* labels = (const int*)d_in[6];
    float* out = (float*)d_out;

    static int configured = 0;
    if (!configured) {
        cudaFuncSetAttribute(gemm_fused, cudaFuncAttributeMaxDynamicSharedMemorySize,
                             DSMEM_BYTES);
        configured = 1;
    }

    prep_kernel<<<NROWS + NC, 256>>>(enc, gamma, beta, heads, tails, arc_w);
    gemm_fused<<<dim3(NC / BN, NROWS / BM), 256, DSMEM_BYTES>>>(labels);
    finish_kernel<<<1, 256>>>(out);
}